// round 3
// baseline (speedup 1.0000x reference)
#include <cuda_runtime.h>
#include <math.h>
#include <cub/block/block_radix_sort.cuh>

// ============================================================================
// GAT 2-layer forward, exact-math O(n log n) reformulation.
// softmax_j(LeakyReLU(s_i + d_j)) @ V via sorted-d prefix tables.
// R3: register-tiled GEMM w/ fused s-reductions, gather-based single-pass
//     dual-branch scans, sort-fused weight computation, fp64 serial scans.
// ============================================================================

#define NB 4
#define NN 4096
#define EPSN 1e-5f
#define NT 32      // scan tiles per chain
#define TS 128     // scan tile size (NT*TS == NN)
#define NSLAB 16

template<int L> struct LP {
  static constexpr int CIN  = (L == 0) ? 64 : 128;
  static constexpr int H    = (L == 0) ? 4 : 1;
  static constexpr int K    = (L == 0) ? 32 : 64;
  static constexpr int COUT = H * K;
  static constexpr int BH   = NB * H;
};

// ---------------- scratch (device globals; no allocation allowed) ----------
__device__ float  g_mu0[NB * 64],  g_rs0[NB * 64];
__device__ float  g_mu1[NB * 128], g_rs1[NB * 128];
__device__ float  g_part0[NB * NSLAB * 64 * 2];
__device__ float  g_part1[NB * NSLAB * 128 * 2];
__device__ float  g_w0p[NB * 64 * 128], g_t0[NB * 128];
__device__ float  g_w1p[NB * 128 * 64], g_t1[NB * 64];
__device__ float  g_feat0[16 * NN * 32];
__device__ float  g_feat1[4 * NN * 64];
__device__ float  g_ssrc0[16 * NN], g_sdst0[16 * NN];
__device__ float  g_ssrc1[4 * NN],  g_sdst1[4 * NN];
__device__ float  g_sortd0[16 * NN];
__device__ int    g_perm0[16 * NN];
__device__ float  g_sortd1[4 * NN];
__device__ int    g_perm1[4 * NN];
__device__ float  g_wP0[16 * NN], g_wQ0[16 * NN];
__device__ float  g_wP1[4 * NN],  g_wQ1[4 * NN];
__device__ float  g_ts0[32 * NT * 33];
__device__ float  g_ts1[8 * NT * 65];
__device__ double g_toff0[32 * NT * 33];
__device__ double g_toff1[8 * NT * 65];
__device__ float  g_pref0[(size_t)16 * 2 * (NN + 1) * 33];
__device__ float  g_pref1[(size_t)4  * 2 * (NN + 1) * 65];
__device__ float  g_cat[(size_t)NB * NN * 128];

// ---------------- instance-norm stats: coalesced slab partials -------------
template<int L>
__global__ void stats_part_kernel(const float* __restrict__ xext) {
  constexpr int C = LP<L>::CIN;
  constexpr int RP = 256 / C;
  const float* x = (L == 0) ? xext : g_cat;
  float* part = (L == 0) ? g_part0 : g_part1;
  int b = blockIdx.x, slab = blockIdx.y;
  int c = threadIdx.x % C, rr = threadIdx.x / C;
  const float* p = x + ((size_t)b * NN + (size_t)slab * 256) * C;
  float s = 0.f, s2 = 0.f;
  for (int i = rr; i < 256; i += RP) {
    float v = p[(size_t)i * C + c];
    s += v; s2 = fmaf(v, v, s2);
  }
  __shared__ float sh[256], sh2[256];
  sh[threadIdx.x] = s; sh2[threadIdx.x] = s2;
  __syncthreads();
  if (rr == 0) {
    float S = s, S2 = s2;
    #pragma unroll
    for (int j = 1; j < RP; ++j) { S += sh[j * C + c]; S2 += sh2[j * C + c]; }
    size_t o = (((size_t)b * NSLAB + slab) * C + c) * 2;
    part[o] = S; part[o + 1] = S2;
  }
}

template<int L>
__global__ void stats_combine_kernel() {
  constexpr int C = LP<L>::CIN;
  const float* part = (L == 0) ? g_part0 : g_part1;
  float* mu = (L == 0) ? g_mu0 : g_mu1;
  float* rs = (L == 0) ? g_rs0 : g_rs1;
  int tid = blockIdx.x * blockDim.x + threadIdx.x;
  if (tid >= NB * C) return;
  int b = tid / C, c = tid % C;
  double S = 0.0, S2 = 0.0;
  for (int slab = 0; slab < NSLAB; ++slab) {
    size_t o = (((size_t)b * NSLAB + slab) * C + c) * 2;
    S += (double)part[o]; S2 += (double)part[o + 1];
  }
  double mean = S / NN;
  double var = S2 / NN - mean * mean;
  mu[tid] = (float)mean;
  rs[tid] = (float)(1.0 / sqrt(var + (double)EPSN));
}

// ---------------- fold instance-norm into GEMM weights ---------------------
template<int L>
__global__ void fold_kernel(const float* __restrict__ w) {
  constexpr int CIN = LP<L>::CIN, K = LP<L>::K, COUT = LP<L>::COUT;
  const float* mu = (L == 0) ? g_mu0 : g_mu1;
  const float* rs = (L == 0) ? g_rs0 : g_rs1;
  float* wp = (L == 0) ? g_w0p : g_w1p;
  float* tv = (L == 0) ? g_t0 : g_t1;
  int tid = blockIdx.x * blockDim.x + threadIdx.x;
  if (tid >= NB * COUT) return;
  int b = tid / COUT, col = tid % COUT;
  int h = col / K, k = col % K;
  float acc = 0.f;
  for (int c = 0; c < CIN; ++c) {
    float wv  = w[((size_t)h * CIN + c) * K + k];
    float wpv = wv * rs[b * CIN + c];
    wp[((size_t)b * CIN + c) * COUT + col] = wpv;
    acc += mu[b * CIN + c] * wpv;
  }
  tv[tid] = acc;
}

// ---------------- GEMM (register-tiled) + fused s_src/s_dst ----------------
// Block: 128 threads, 32 rows x COUT cols. Thread: RT rows x 4 cols.
template<int L>
__global__ void gemm_kernel(const float* __restrict__ xext,
                            const float* __restrict__ a_src,
                            const float* __restrict__ a_dst) {
  constexpr int CIN = LP<L>::CIN, H = LP<L>::H, K = LP<L>::K, COUT = LP<L>::COUT;
  constexpr int NC = COUT / 4;   // col-threads (32 / 16)
  constexpr int NR = 128 / NC;   // row-threads (4 / 8)
  constexpr int RT = 32 / NR;    // rows per thread (8 / 4)
  constexpr int G  = NC / H;     // lanes per head group (8 / 16)
  const float* x  = (L == 0) ? xext : g_cat;
  const float* wp = (L == 0) ? g_w0p : g_w1p;
  const float* tv = (L == 0) ? g_t0 : g_t1;
  float* feat = (L == 0) ? g_feat0 : g_feat1;
  float* ssrc = (L == 0) ? g_ssrc0 : g_ssrc1;
  float* sdst = (L == 0) ? g_sdst0 : g_sdst1;
  __shared__ float ws[CIN * COUT];
  __shared__ float xs[32 * CIN];
  int b = blockIdx.x, rt = blockIdx.y;
  int tid = threadIdx.x;
  const float4* wsrc = (const float4*)(wp + (size_t)b * CIN * COUT);
  for (int i = tid; i < CIN * COUT / 4; i += 128) ((float4*)ws)[i] = wsrc[i];
  const float4* xsrc = (const float4*)(x + ((size_t)b * NN + (size_t)rt * 32) * CIN);
  for (int i = tid; i < 32 * CIN / 4; i += 128) ((float4*)xs)[i] = xsrc[i];
  __syncthreads();
  int tc = tid % NC, tr = tid / NC;
  int col0 = tc * 4, r0 = tr * RT;
  float4 tv4 = *(const float4*)(tv + b * COUT + col0);
  float acc[RT][4];
  #pragma unroll
  for (int i = 0; i < RT; ++i) {
    acc[i][0] = -tv4.x; acc[i][1] = -tv4.y; acc[i][2] = -tv4.z; acc[i][3] = -tv4.w;
  }
  #pragma unroll 4
  for (int c = 0; c < CIN; ++c) {
    float4 wv = *(const float4*)(ws + c * COUT + col0);
    #pragma unroll
    for (int i = 0; i < RT; ++i) {
      float xv = xs[(r0 + i) * CIN + c];
      acc[i][0] = fmaf(xv, wv.x, acc[i][0]);
      acc[i][1] = fmaf(xv, wv.y, acc[i][1]);
      acc[i][2] = fmaf(xv, wv.z, acc[i][2]);
      acc[i][3] = fmaf(xv, wv.w, acc[i][3]);
    }
  }
  int h = col0 / K, k0 = col0 % K;
  float4 as4 = *(const float4*)(a_src + col0);
  float4 ad4 = *(const float4*)(a_dst + col0);
  int nbase = rt * 32 + r0;
  float* fo = feat + (((size_t)b * H + h) * NN + nbase) * K + k0;
  size_t sbase = ((size_t)b * H + h) * NN + nbase;
  #pragma unroll
  for (int i = 0; i < RT; ++i) {
    *(float4*)(fo + (size_t)i * K) = make_float4(acc[i][0], acc[i][1], acc[i][2], acc[i][3]);
    float s1 = acc[i][0] * as4.x + acc[i][1] * as4.y + acc[i][2] * as4.z + acc[i][3] * as4.w;
    float s2 = acc[i][0] * ad4.x + acc[i][1] * ad4.y + acc[i][2] * ad4.z + acc[i][3] * ad4.w;
    #pragma unroll
    for (int off = 1; off < G; off <<= 1) {
      s1 += __shfl_xor_sync(0xffffffffu, s1, off);
      s2 += __shfl_xor_sync(0xffffffffu, s2, off);
    }
    if ((tc & (G - 1)) == 0) {
      ssrc[sbase + i] = s1;
      sdst[sbase + i] = s2;
    }
  }
}

// ---------------- radix sort of d (descending) + wP/wQ weights -------------
template<int L>
__global__ void sort_kernel() {
  constexpr int BT = 512, IPT = NN / BT;  // 8 items per thread
  const float* sdstA = (L == 0) ? g_sdst0 : g_sdst1;
  float* sortd = (L == 0) ? g_sortd0 : g_sortd1;
  int*   perm  = (L == 0) ? g_perm0 : g_perm1;
  float* wP = (L == 0) ? g_wP0 : g_wP1;
  float* wQ = (L == 0) ? g_wQ0 : g_wQ1;
  using BRS = cub::BlockRadixSort<float, BT, IPT, int>;
  __shared__ typename BRS::TempStorage ts;
  __shared__ float sdmax;
  int bh = blockIdx.x;
  const float* src = sdstA + (size_t)bh * NN;
  float keys[IPT]; int vals[IPT];
  int base = threadIdx.x * IPT;
  #pragma unroll
  for (int i = 0; i < IPT; ++i) { keys[i] = src[base + i]; vals[i] = base + i; }
  BRS(ts).SortDescending(keys, vals);
  if (threadIdx.x == 0) sdmax = keys[0];
  __syncthreads();
  float dmax = sdmax;
  #pragma unroll
  for (int i = 0; i < IPT; ++i) {
    size_t o = (size_t)bh * NN + base + i;
    sortd[o] = keys[i];
    perm[o]  = vals[i];
    wP[o] = expf(keys[i] - dmax);
    wQ[o] = expf(0.2f * (keys[i] - dmax));
  }
}

// ---------------- scan pass A: per-tile sums, both branches ----------------
template<int L>
__global__ void scanA_kernel() {
  constexpr int K = LP<L>::K;
  constexpr int RS = 128 / K;   // row streams
  const float* feat = (L == 0) ? g_feat0 : g_feat1;
  const int*   perm = (L == 0) ? g_perm0 : g_perm1;
  const float* wPg = (L == 0) ? g_wP0 : g_wP1;
  const float* wQg = (L == 0) ? g_wQ0 : g_wQ1;
  float* tsum = (L == 0) ? g_ts0 : g_ts1;
  int bh = blockIdx.x, tile = blockIdx.y, pos0 = tile * TS;
  int k = threadIdx.x % K, r = threadIdx.x / K;
  const float* fe = feat + (size_t)bh * NN * K;
  const int*   pm = perm + (size_t)bh * NN + pos0;
  const float* wp = wPg + (size_t)bh * NN + pos0;
  const float* wq = wQg + (size_t)bh * NN + pos0;
  float aP = 0.f, aQ = 0.f;
  for (int i = r; i < TS; i += RS) {
    int p = pm[i];
    float v = fe[(size_t)p * K + k];
    aP = fmaf(wp[i], v, aP);
    aQ = fmaf(wq[i], v, aQ);
  }
  __shared__ float redP[128], redQ[128];
  redP[threadIdx.x] = aP; redQ[threadIdx.x] = aQ;
  __syncthreads();
  size_t tbP = ((size_t)(bh * 2)     * NT + tile) * (K + 1);
  size_t tbQ = ((size_t)(bh * 2 + 1) * NT + tile) * (K + 1);
  if (r == 0) {
    float sP = aP, sQ = aQ;
    #pragma unroll
    for (int j = 1; j < RS; ++j) { sP += redP[j * K + k]; sQ += redQ[j * K + k]; }
    tsum[tbP + k] = sP;
    tsum[tbQ + k] = sQ;
  }
  if (threadIdx.x < 32) {
    float wa = 0.f, wb = 0.f;
    #pragma unroll
    for (int i = 0; i < TS / 32; ++i) {
      wa += wp[threadIdx.x + 32 * i];
      wb += wq[threadIdx.x + 32 * i];
    }
    #pragma unroll
    for (int o = 16; o; o >>= 1) {
      wa += __shfl_down_sync(0xffffffffu, wa, o);
      wb += __shfl_down_sync(0xffffffffu, wb, o);
    }
    if (threadIdx.x == 0) { tsum[tbP + K] = wa; tsum[tbQ + K] = wb; }
  }
}

// ---------------- scan pass B: tile offsets (fp64) + totals -----------------
template<int L>
__global__ void scanB_kernel() {
  constexpr int K = LP<L>::K;
  const float* tsum = (L == 0) ? g_ts0 : g_ts1;
  double* toff = (L == 0) ? g_toff0 : g_toff1;
  float* pref = (L == 0) ? g_pref0 : g_pref1;
  int bh = blockIdx.x;
  int t = threadIdx.x;
  if (t >= 2 * (K + 1)) return;
  int branch = t / (K + 1), d = t % (K + 1);
  int chain = bh * 2 + branch;
  double run = 0.0;
  for (int tt = 0; tt < NT; ++tt) {
    size_t idx = ((size_t)chain * NT + tt) * (K + 1) + d;
    toff[idx] = run;
    run += (double)tsum[idx];
  }
  pref[((size_t)chain * (NN + 1) + NN) * (K + 1) + d] = (float)run;
}

// ---------------- scan pass C: tile-local exclusive scans (fp64 run) --------
template<int L>
__global__ void scanC_kernel() {
  constexpr int K = LP<L>::K;
  const float* feat = (L == 0) ? g_feat0 : g_feat1;
  const int*   perm = (L == 0) ? g_perm0 : g_perm1;
  const float* wPg = (L == 0) ? g_wP0 : g_wP1;
  const float* wQg = (L == 0) ? g_wQ0 : g_wQ1;
  const double* toff = (L == 0) ? g_toff0 : g_toff1;
  float* pref = (L == 0) ? g_pref0 : g_pref1;
  __shared__ float vs[TS * K];
  __shared__ float wPs[TS], wQs[TS];
  __shared__ int pm[TS];
  int bh = blockIdx.x, tile = blockIdx.y, pos0 = tile * TS;
  int tid = threadIdx.x;
  {
    size_t o = (size_t)bh * NN + pos0 + tid;
    pm[tid] = perm[o];
    wPs[tid] = wPg[o];
    wQs[tid] = wQg[o];
  }
  __syncthreads();
  const float* fe = feat + (size_t)bh * NN * K;
  for (int e = tid; e < TS * K; e += 128) {
    int i = e / K, k = e % K;
    vs[e] = fe[(size_t)pm[i] * K + k];
  }
  __syncthreads();
  int d = tid;
  if (d <= K) {
    double runP = toff[((size_t)(bh * 2)     * NT + tile) * (K + 1) + d];
    double runQ = toff[((size_t)(bh * 2 + 1) * NT + tile) * (K + 1) + d];
    float* outP = pref + ((size_t)(bh * 2)     * (NN + 1) + pos0) * (K + 1) + d;
    float* outQ = pref + ((size_t)(bh * 2 + 1) * (NN + 1) + pos0) * (K + 1) + d;
    for (int i = 0; i < TS; ++i) {
      outP[(size_t)i * (K + 1)] = (float)runP;
      outQ[(size_t)i * (K + 1)] = (float)runQ;
      float vv = (d < K) ? vs[i * K + d] : 1.0f;
      runP += (double)(wPs[i] * vv);
      runQ += (double)(wQs[i] * vv);
    }
  }
}

// ---------------- per-row combine: parallel search + prefix gather ----------
template<int L>
__global__ void rows_kernel(const float* __restrict__ bias,
                            float* __restrict__ outext) {
  constexpr int K = LP<L>::K, H = LP<L>::H;
  constexpr bool ELU = (L == 0);
  constexpr int RPB = 128;
  const float* ssrc  = (L == 0) ? g_ssrc0 : g_ssrc1;
  const float* sortd = (L == 0) ? g_sortd0 : g_sortd1;
  const float* pref  = (L == 0) ? g_pref0 : g_pref1;
  float* out = (L == 0) ? g_cat : outext;

  int bh = blockIdx.x;
  __shared__ float sd[NN];
  __shared__ int   ms[RPB];
  __shared__ float al[RPB], be[RPB];
  __shared__ float qt[K + 1];
  __shared__ float bs[K];
  for (int i = threadIdx.x; i < NN; i += 256) sd[i] = sortd[(size_t)bh * NN + i];
  const float* prefP = pref + (size_t)(bh * 2) * (NN + 1) * (K + 1);
  const float* prefQ = prefP + (size_t)(NN + 1) * (K + 1);
  if (threadIdx.x < K + 1) qt[threadIdx.x] = prefQ[(size_t)NN * (K + 1) + threadIdx.x];
  if (threadIdx.x < K) bs[threadIdx.x] = bias[threadIdx.x];
  __syncthreads();

  float dmax = sd[0];
  int row0 = blockIdx.y * RPB;

  if (threadIdx.x < RPB) {
    int r = row0 + threadIdx.x;
    float s = ssrc[(size_t)bh * NN + r];
    float T = s + dmax;
    if (T > 0.f) { al[threadIdx.x] = 1.f; be[threadIdx.x] = expf(-0.8f * T); }
    else         { al[threadIdx.x] = expf(0.8f * T); be[threadIdx.x] = 1.f; }
    float thr = -s;
    int lo = 0, hi = NN;
    while (lo < hi) {
      int mid = (lo + hi) >> 1;
      if (sd[mid] > thr) lo = mid + 1; else hi = mid;
    }
    ms[threadIdx.x] = lo;
  }
  __syncthreads();

  int warp = threadIdx.x >> 5, lane = threadIdx.x & 31;
  int b = bh / H, h = bh % H;
  for (int rr = warp; rr < RPB; rr += 8) {
    int r = row0 + rr;
    int m = ms[rr];
    float alpha = al[rr], beta = be[rr];
    const float* pP = prefP + (size_t)m * (K + 1);
    const float* pQ = prefQ + (size_t)m * (K + 1);
    float den = alpha * pP[K] + beta * (qt[K] - pQ[K]);
    float inv = 1.f / den;
    #pragma unroll
    for (int k = lane; k < K; k += 32) {
      float num = alpha * pP[k] + beta * (qt[k] - pQ[k]);
      float v = num * inv + bs[k];
      size_t oi = ((size_t)b * NN + r) * (size_t)(H * K) + (size_t)h * K + k;
      if (ELU) out[oi] = (v > 0.f) ? v : (expf(v) - 1.f);
      else     out[oi] = v;
    }
  }
}

// ---------------- launch ----------------------------------------------------
extern "C" void kernel_launch(void* const* d_in, const int* in_sizes, int n_in,
                              void* d_out, int out_size) {
  (void)in_sizes; (void)n_in; (void)out_size;
  const float* x      = (const float*)d_in[0];
  const float* w0     = (const float*)d_in[1];
  const float* a_src0 = (const float*)d_in[2];
  const float* a_dst0 = (const float*)d_in[3];
  const float* b0     = (const float*)d_in[4];
  const float* w1     = (const float*)d_in[5];
  const float* a_src1 = (const float*)d_in[6];
  const float* a_dst1 = (const float*)d_in[7];
  const float* b1     = (const float*)d_in[8];
  float* out = (float*)d_out;

  // ---- layer 0 ----
  stats_part_kernel<0><<<dim3(NB, NSLAB), 256>>>(x);
  stats_combine_kernel<0><<<2, 128>>>();
  fold_kernel<0><<<2, 256>>>(w0);
  gemm_kernel<0><<<dim3(NB, NN / 32), 128>>>(x, a_src0, a_dst0);
  sort_kernel<0><<<16, 512>>>();
  scanA_kernel<0><<<dim3(16, NT), 128>>>();
  scanB_kernel<0><<<16, 66>>>();
  scanC_kernel<0><<<dim3(16, NT), 128>>>();
  rows_kernel<0><<<dim3(16, NN / 128), 256>>>(b0, nullptr);

  // ---- layer 1 ----
  stats_part_kernel<1><<<dim3(NB, NSLAB), 256>>>(nullptr);
  stats_combine_kernel<1><<<4, 128>>>();
  fold_kernel<1><<<1, 256>>>(w1);
  gemm_kernel<1><<<dim3(NB, NN / 32), 128>>>(nullptr, a_src1, a_dst1);
  sort_kernel<1><<<4, 512>>>();
  scanA_kernel<1><<<dim3(4, NT), 128>>>();
  scanB_kernel<1><<<4, 130>>>();
  scanC_kernel<1><<<dim3(4, NT), 128>>>();
  rows_kernel<1><<<dim3(4, NN / 128), 256>>>(b1, out);
}

// round 4
// speedup vs baseline: 1.4598x; 1.4598x over previous
#include <cuda_runtime.h>
#include <math.h>
#include <cub/block/block_radix_sort.cuh>

// ============================================================================
// GAT 2-layer forward, exact-math O(n log n) reformulation.
// softmax_j(LeakyReLU(s_i + d_j)) @ V via sorted-d tables:
//   P = forward prefix of e^{d-dmax}*v  (rows with s_i+d_j > 0)
//   Q = REVERSE suffix of e^{0.2(d-dmax)}*v  (no cancellation, fp32-safe)
// R4: all-fp32 scans, suffix-Q, parallel P/Q chains, merged fold+stats.
// ============================================================================

#define NB 4
#define NN 4096
#define EPSN 1e-5f
#define NT 32      // scan tiles per chain
#define TS 128     // scan tile size (NT*TS == NN)
#define NSLAB 16

template<int L> struct LP {
  static constexpr int CIN  = (L == 0) ? 64 : 128;
  static constexpr int H    = (L == 0) ? 4 : 1;
  static constexpr int K    = (L == 0) ? 32 : 64;
  static constexpr int COUT = H * K;
  static constexpr int BH   = NB * H;
};

// ---------------- scratch (device globals; no allocation allowed) ----------
__device__ float  g_part0[NB * NSLAB * 64 * 2];
__device__ float  g_part1[NB * NSLAB * 128 * 2];
__device__ float  g_w0p[NB * 64 * 128], g_t0[NB * 128];
__device__ float  g_w1p[NB * 128 * 64], g_t1[NB * 64];
__device__ float  g_feat0[16 * NN * 32];
__device__ float  g_feat1[4 * NN * 64];
__device__ float  g_ssrc0[16 * NN], g_sdst0[16 * NN];
__device__ float  g_ssrc1[4 * NN],  g_sdst1[4 * NN];
__device__ float  g_sortd0[16 * NN];
__device__ int    g_perm0[16 * NN];
__device__ float  g_sortd1[4 * NN];
__device__ int    g_perm1[4 * NN];
__device__ float  g_wP0[16 * NN], g_wQ0[16 * NN];
__device__ float  g_wP1[4 * NN],  g_wQ1[4 * NN];
__device__ float  g_ts0[32 * NT * 33];
__device__ float  g_ts1[8 * NT * 65];
__device__ float  g_toff0[32 * NT * 33];
__device__ float  g_toff1[8 * NT * 65];
__device__ float  g_pref0[(size_t)16 * 2 * (NN + 1) * 33];
__device__ float  g_pref1[(size_t)4  * 2 * (NN + 1) * 65];
__device__ float  g_cat[(size_t)NB * NN * 128];

// ---------------- instance-norm stats: coalesced slab partials -------------
template<int L>
__global__ void stats_part_kernel(const float* __restrict__ xext) {
  constexpr int C = LP<L>::CIN;
  constexpr int RP = 256 / C;
  const float* x = (L == 0) ? xext : g_cat;
  float* part = (L == 0) ? g_part0 : g_part1;
  int b = blockIdx.x, slab = blockIdx.y;
  int c = threadIdx.x % C, rr = threadIdx.x / C;
  const float* p = x + ((size_t)b * NN + (size_t)slab * 256) * C;
  float s = 0.f, s2 = 0.f;
  for (int i = rr; i < 256; i += RP) {
    float v = p[(size_t)i * C + c];
    s += v; s2 = fmaf(v, v, s2);
  }
  __shared__ float sh[256], sh2[256];
  sh[threadIdx.x] = s; sh2[threadIdx.x] = s2;
  __syncthreads();
  if (rr == 0) {
    float S = s, S2 = s2;
    #pragma unroll
    for (int j = 1; j < RP; ++j) { S += sh[j * C + c]; S2 += sh2[j * C + c]; }
    size_t o = (((size_t)b * NSLAB + slab) * C + c) * 2;
    part[o] = S; part[o + 1] = S2;
  }
}

// ---------------- combine stats + fold instance-norm into weights ----------
// One block per batch b. Threads: first CIN combine, then COUT fold.
template<int L>
__global__ void fold_kernel(const float* __restrict__ w) {
  constexpr int CIN = LP<L>::CIN, K = LP<L>::K, COUT = LP<L>::COUT;
  const float* part = (L == 0) ? g_part0 : g_part1;
  float* wp = (L == 0) ? g_w0p : g_w1p;
  float* tv = (L == 0) ? g_t0 : g_t1;
  __shared__ float mu[CIN], rs[CIN];
  int b = blockIdx.x, tid = threadIdx.x;
  if (tid < CIN) {
    double S = 0.0, S2 = 0.0;
    for (int slab = 0; slab < NSLAB; ++slab) {
      size_t o = (((size_t)b * NSLAB + slab) * CIN + tid) * 2;
      S += (double)part[o]; S2 += (double)part[o + 1];
    }
    double mean = S / NN;
    double var = S2 / NN - mean * mean;
    mu[tid] = (float)mean;
    rs[tid] = (float)(1.0 / sqrt(var + (double)EPSN));
  }
  __syncthreads();
  if (tid < COUT) {
    int h = tid / K, k = tid % K;
    float acc = 0.f;
    for (int c = 0; c < CIN; ++c) {
      float wv  = w[((size_t)h * CIN + c) * K + k];
      float wpv = wv * rs[c];
      wp[((size_t)b * CIN + c) * COUT + tid] = wpv;
      acc = fmaf(mu[c], wpv, acc);
    }
    tv[b * COUT + tid] = acc;
  }
}

// ---------------- GEMM (register-tiled) + fused s_src/s_dst ----------------
template<int L>
__global__ void gemm_kernel(const float* __restrict__ xext,
                            const float* __restrict__ a_src,
                            const float* __restrict__ a_dst) {
  constexpr int CIN = LP<L>::CIN, H = LP<L>::H, K = LP<L>::K, COUT = LP<L>::COUT;
  constexpr int NC = COUT / 4;
  constexpr int NR = 128 / NC;
  constexpr int RT = 32 / NR;
  constexpr int G  = NC / H;
  const float* x  = (L == 0) ? xext : g_cat;
  const float* wp = (L == 0) ? g_w0p : g_w1p;
  const float* tv = (L == 0) ? g_t0 : g_t1;
  float* feat = (L == 0) ? g_feat0 : g_feat1;
  float* ssrc = (L == 0) ? g_ssrc0 : g_ssrc1;
  float* sdst = (L == 0) ? g_sdst0 : g_sdst1;
  __shared__ float ws[CIN * COUT];
  __shared__ float xs[32 * CIN];
  int b = blockIdx.x, rt = blockIdx.y;
  int tid = threadIdx.x;
  const float4* wsrc = (const float4*)(wp + (size_t)b * CIN * COUT);
  for (int i = tid; i < CIN * COUT / 4; i += 128) ((float4*)ws)[i] = wsrc[i];
  const float4* xsrc = (const float4*)(x + ((size_t)b * NN + (size_t)rt * 32) * CIN);
  for (int i = tid; i < 32 * CIN / 4; i += 128) ((float4*)xs)[i] = xsrc[i];
  __syncthreads();
  int tc = tid % NC, tr = tid / NC;
  int col0 = tc * 4, r0 = tr * RT;
  float4 tv4 = *(const float4*)(tv + b * COUT + col0);
  float acc[RT][4];
  #pragma unroll
  for (int i = 0; i < RT; ++i) {
    acc[i][0] = -tv4.x; acc[i][1] = -tv4.y; acc[i][2] = -tv4.z; acc[i][3] = -tv4.w;
  }
  #pragma unroll 4
  for (int c = 0; c < CIN; ++c) {
    float4 wv = *(const float4*)(ws + c * COUT + col0);
    #pragma unroll
    for (int i = 0; i < RT; ++i) {
      float xv = xs[(r0 + i) * CIN + c];
      acc[i][0] = fmaf(xv, wv.x, acc[i][0]);
      acc[i][1] = fmaf(xv, wv.y, acc[i][1]);
      acc[i][2] = fmaf(xv, wv.z, acc[i][2]);
      acc[i][3] = fmaf(xv, wv.w, acc[i][3]);
    }
  }
  int h = col0 / K, k0 = col0 % K;
  float4 as4 = *(const float4*)(a_src + col0);
  float4 ad4 = *(const float4*)(a_dst + col0);
  int nbase = rt * 32 + r0;
  float* fo = feat + (((size_t)b * H + h) * NN + nbase) * K + k0;
  size_t sbase = ((size_t)b * H + h) * NN + nbase;
  #pragma unroll
  for (int i = 0; i < RT; ++i) {
    *(float4*)(fo + (size_t)i * K) = make_float4(acc[i][0], acc[i][1], acc[i][2], acc[i][3]);
    float s1 = acc[i][0] * as4.x + acc[i][1] * as4.y + acc[i][2] * as4.z + acc[i][3] * as4.w;
    float s2 = acc[i][0] * ad4.x + acc[i][1] * ad4.y + acc[i][2] * ad4.z + acc[i][3] * ad4.w;
    #pragma unroll
    for (int off = 1; off < G; off <<= 1) {
      s1 += __shfl_xor_sync(0xffffffffu, s1, off);
      s2 += __shfl_xor_sync(0xffffffffu, s2, off);
    }
    if ((tc & (G - 1)) == 0) {
      ssrc[sbase + i] = s1;
      sdst[sbase + i] = s2;
    }
  }
}

// ---------------- radix sort of d (descending) + wP/wQ weights -------------
template<int L>
__global__ void sort_kernel() {
  constexpr int BT = 512, IPT = NN / BT;
  const float* sdstA = (L == 0) ? g_sdst0 : g_sdst1;
  float* sortd = (L == 0) ? g_sortd0 : g_sortd1;
  int*   perm  = (L == 0) ? g_perm0 : g_perm1;
  float* wP = (L == 0) ? g_wP0 : g_wP1;
  float* wQ = (L == 0) ? g_wQ0 : g_wQ1;
  using BRS = cub::BlockRadixSort<float, BT, IPT, int>;
  __shared__ typename BRS::TempStorage ts;
  __shared__ float sdmax;
  int bh = blockIdx.x;
  const float* src = sdstA + (size_t)bh * NN;
  float keys[IPT]; int vals[IPT];
  int base = threadIdx.x * IPT;
  #pragma unroll
  for (int i = 0; i < IPT; ++i) { keys[i] = src[base + i]; vals[i] = base + i; }
  BRS(ts).SortDescending(keys, vals);
  if (threadIdx.x == 0) sdmax = keys[0];
  __syncthreads();
  float dmax = sdmax;
  #pragma unroll
  for (int i = 0; i < IPT; ++i) {
    size_t o = (size_t)bh * NN + base + i;
    sortd[o] = keys[i];
    perm[o]  = vals[i];
    wP[o] = expf(keys[i] - dmax);
    wQ[o] = expf(0.2f * (keys[i] - dmax));
  }
}

// ---------------- scan pass A: per-tile sums, both branches ----------------
template<int L>
__global__ void scanA_kernel() {
  constexpr int K = LP<L>::K;
  constexpr int RS = 128 / K;
  const float* feat = (L == 0) ? g_feat0 : g_feat1;
  const int*   perm = (L == 0) ? g_perm0 : g_perm1;
  const float* wPg = (L == 0) ? g_wP0 : g_wP1;
  const float* wQg = (L == 0) ? g_wQ0 : g_wQ1;
  float* tsum = (L == 0) ? g_ts0 : g_ts1;
  int bh = blockIdx.x, tile = blockIdx.y, pos0 = tile * TS;
  int k = threadIdx.x % K, r = threadIdx.x / K;
  const float* fe = feat + (size_t)bh * NN * K;
  const int*   pm = perm + (size_t)bh * NN + pos0;
  const float* wp = wPg + (size_t)bh * NN + pos0;
  const float* wq = wQg + (size_t)bh * NN + pos0;
  float aP = 0.f, aQ = 0.f;
  for (int i = r; i < TS; i += RS) {
    int p = pm[i];
    float v = fe[(size_t)p * K + k];
    aP = fmaf(wp[i], v, aP);
    aQ = fmaf(wq[i], v, aQ);
  }
  __shared__ float redP[128], redQ[128];
  redP[threadIdx.x] = aP; redQ[threadIdx.x] = aQ;
  __syncthreads();
  size_t tbP = ((size_t)(bh * 2)     * NT + tile) * (K + 1);
  size_t tbQ = ((size_t)(bh * 2 + 1) * NT + tile) * (K + 1);
  if (r == 0) {
    float sP = aP, sQ = aQ;
    #pragma unroll
    for (int j = 1; j < RS; ++j) { sP += redP[j * K + k]; sQ += redQ[j * K + k]; }
    tsum[tbP + k] = sP;
    tsum[tbQ + k] = sQ;
  }
  if (threadIdx.x < 32) {
    float wa = 0.f, wb = 0.f;
    #pragma unroll
    for (int i = 0; i < TS / 32; ++i) {
      wa += wp[threadIdx.x + 32 * i];
      wb += wq[threadIdx.x + 32 * i];
    }
    #pragma unroll
    for (int o = 16; o; o >>= 1) {
      wa += __shfl_down_sync(0xffffffffu, wa, o);
      wb += __shfl_down_sync(0xffffffffu, wb, o);
    }
    if (threadIdx.x == 0) { tsum[tbP + K] = wa; tsum[tbQ + K] = wb; }
  }
}

// ---------------- scan pass B: tile offsets. P forward, Q reverse ----------
template<int L>
__global__ void scanB_kernel() {
  constexpr int K = LP<L>::K;
  const float* tsum = (L == 0) ? g_ts0 : g_ts1;
  float* toff = (L == 0) ? g_toff0 : g_toff1;
  float* pref = (L == 0) ? g_pref0 : g_pref1;
  int bh = blockIdx.x;
  int t = threadIdx.x;
  if (t >= 2 * (K + 1)) return;
  int branch = t / (K + 1), d = t % (K + 1);
  int chain = bh * 2 + branch;
  size_t cb = (size_t)chain * NT;
  float run = 0.f;
  if (branch == 0) {
    for (int tt = 0; tt < NT; ++tt) {
      size_t idx = (cb + tt) * (K + 1) + d;
      toff[idx] = run;
      run += tsum[idx];
    }
    pref[((size_t)chain * (NN + 1) + NN) * (K + 1) + d] = run;  // P total
  } else {
    for (int tt = NT - 1; tt >= 0; --tt) {
      size_t idx = (cb + tt) * (K + 1) + d;
      toff[idx] = run;            // sum of LATER tiles
      run += tsum[idx];
    }
    pref[((size_t)chain * (NN + 1) + NN) * (K + 1) + d] = 0.f;  // Q suffix at NN
  }
}

// ---------------- scan pass C: tile-local scans. P fwd excl, Q rev incl ----
// 256 threads: tid in [0,K] -> P chain dim tid; tid in [128,128+K] -> Q chain.
template<int L>
__global__ void scanC_kernel() {
  constexpr int K = LP<L>::K;
  const float* feat = (L == 0) ? g_feat0 : g_feat1;
  const int*   perm = (L == 0) ? g_perm0 : g_perm1;
  const float* wPg = (L == 0) ? g_wP0 : g_wP1;
  const float* wQg = (L == 0) ? g_wQ0 : g_wQ1;
  const float* toff = (L == 0) ? g_toff0 : g_toff1;
  float* pref = (L == 0) ? g_pref0 : g_pref1;
  __shared__ float vs[TS * K];
  __shared__ float wPs[TS], wQs[TS];
  __shared__ int pm[TS];
  int bh = blockIdx.x, tile = blockIdx.y, pos0 = tile * TS;
  int tid = threadIdx.x;
  if (tid < TS) {
    size_t o = (size_t)bh * NN + pos0 + tid;
    pm[tid] = perm[o];
    wPs[tid] = wPg[o];
    wQs[tid] = wQg[o];
  }
  __syncthreads();
  const float* fe = feat + (size_t)bh * NN * K;
  for (int e = tid; e < TS * K; e += 256) {
    int i = e / K, k = e % K;
    vs[e] = fe[(size_t)pm[i] * K + k];
  }
  __syncthreads();
  if (tid <= K) {
    // P: forward exclusive
    int d = tid;
    float run = toff[((size_t)(bh * 2) * NT + tile) * (K + 1) + d];
    float* outP = pref + ((size_t)(bh * 2) * (NN + 1) + pos0) * (K + 1) + d;
    if (d < K) {
      for (int i = 0; i < TS; ++i) {
        outP[(size_t)i * (K + 1)] = run;
        run = fmaf(wPs[i], vs[i * K + d], run);
      }
    } else {
      for (int i = 0; i < TS; ++i) {
        outP[(size_t)i * (K + 1)] = run;
        run += wPs[i];
      }
    }
  } else if (tid >= 128 && tid <= 128 + K) {
    // Q: reverse inclusive (suffix sums)
    int d = tid - 128;
    float run = toff[((size_t)(bh * 2 + 1) * NT + tile) * (K + 1) + d];
    float* outQ = pref + ((size_t)(bh * 2 + 1) * (NN + 1) + pos0) * (K + 1) + d;
    if (d < K) {
      for (int i = TS - 1; i >= 0; --i) {
        run = fmaf(wQs[i], vs[i * K + d], run);
        outQ[(size_t)i * (K + 1)] = run;
      }
    } else {
      for (int i = TS - 1; i >= 0; --i) {
        run += wQs[i];
        outQ[(size_t)i * (K + 1)] = run;
      }
    }
  }
}

// ---------------- per-row combine: parallel search + prefix gather ----------
template<int L>
__global__ void rows_kernel(const float* __restrict__ bias,
                            float* __restrict__ outext) {
  constexpr int K = LP<L>::K, H = LP<L>::H;
  constexpr bool ELU = (L == 0);
  constexpr int RPB = 128;
  const float* ssrc  = (L == 0) ? g_ssrc0 : g_ssrc1;
  const float* sortd = (L == 0) ? g_sortd0 : g_sortd1;
  const float* pref  = (L == 0) ? g_pref0 : g_pref1;
  float* out = (L == 0) ? g_cat : outext;

  int bh = blockIdx.x;
  __shared__ float sd[NN];
  __shared__ int   ms[RPB];
  __shared__ float al[RPB], be[RPB];
  __shared__ float bs[K];
  for (int i = threadIdx.x; i < NN; i += 256) sd[i] = sortd[(size_t)bh * NN + i];
  const float* prefP = pref + (size_t)(bh * 2) * (NN + 1) * (K + 1);
  const float* prefQ = prefP + (size_t)(NN + 1) * (K + 1);
  if (threadIdx.x < K) bs[threadIdx.x] = bias[threadIdx.x];
  __syncthreads();

  float dmax = sd[0];
  int row0 = blockIdx.y * RPB;

  if (threadIdx.x < RPB) {
    int r = row0 + threadIdx.x;
    float s = ssrc[(size_t)bh * NN + r];
    float T = s + dmax;
    if (T > 0.f) { al[threadIdx.x] = 1.f; be[threadIdx.x] = expf(-0.8f * T); }
    else         { al[threadIdx.x] = expf(0.8f * T); be[threadIdx.x] = 1.f; }
    float thr = -s;
    int lo = 0, hi = NN;
    while (lo < hi) {
      int mid = (lo + hi) >> 1;
      if (sd[mid] > thr) lo = mid + 1; else hi = mid;
    }
    ms[threadIdx.x] = lo;
  }
  __syncthreads();

  int warp = threadIdx.x >> 5, lane = threadIdx.x & 31;
  int b = bh / H, h = bh % H;
  for (int rr = warp; rr < RPB; rr += 8) {
    int r = row0 + rr;
    int m = ms[rr];
    float alpha = al[rr], beta = be[rr];
    const float* pP = prefP + (size_t)m * (K + 1);
    const float* pQ = prefQ + (size_t)m * (K + 1);
    float den = alpha * pP[K] + beta * pQ[K];
    float inv = 1.f / den;
    #pragma unroll
    for (int k = lane; k < K; k += 32) {
      float num = alpha * pP[k] + beta * pQ[k];
      float v = num * inv + bs[k];
      size_t oi = ((size_t)b * NN + r) * (size_t)(H * K) + (size_t)h * K + k;
      if (ELU) out[oi] = (v > 0.f) ? v : (expf(v) - 1.f);
      else     out[oi] = v;
    }
  }
}

// ---------------- launch ----------------------------------------------------
extern "C" void kernel_launch(void* const* d_in, const int* in_sizes, int n_in,
                              void* d_out, int out_size) {
  (void)in_sizes; (void)n_in; (void)out_size;
  const float* x      = (const float*)d_in[0];
  const float* w0     = (const float*)d_in[1];
  const float* a_src0 = (const float*)d_in[2];
  const float* a_dst0 = (const float*)d_in[3];
  const float* b0     = (const float*)d_in[4];
  const float* w1     = (const float*)d_in[5];
  const float* a_src1 = (const float*)d_in[6];
  const float* a_dst1 = (const float*)d_in[7];
  const float* b1     = (const float*)d_in[8];
  float* out = (float*)d_out;

  // ---- layer 0 ----
  stats_part_kernel<0><<<dim3(NB, NSLAB), 256>>>(x);
  fold_kernel<0><<<NB, 128>>>(w0);
  gemm_kernel<0><<<dim3(NB, NN / 32), 128>>>(x, a_src0, a_dst0);
  sort_kernel<0><<<16, 512>>>();
  scanA_kernel<0><<<dim3(16, NT), 128>>>();
  scanB_kernel<0><<<16, 128>>>();
  scanC_kernel<0><<<dim3(16, NT), 256>>>();
  rows_kernel<0><<<dim3(16, NN / 128), 256>>>(b0, nullptr);

  // ---- layer 1 ----
  stats_part_kernel<1><<<dim3(NB, NSLAB), 256>>>(nullptr);
  fold_kernel<1><<<NB, 128>>>(w1);
  gemm_kernel<1><<<dim3(NB, NN / 32), 128>>>(nullptr, a_src1, a_dst1);
  sort_kernel<1><<<4, 512>>>();
  scanA_kernel<1><<<dim3(4, NT), 128>>>();
  scanB_kernel<1><<<4, 160>>>();
  scanC_kernel<1><<<dim3(4, NT), 256>>>();
  rows_kernel<1><<<dim3(4, NN / 128), 256>>>(b1, out);
}

// round 5
// speedup vs baseline: 1.8090x; 1.2392x over previous
#include <cuda_runtime.h>
#include <math.h>
#include <cub/block/block_radix_sort.cuh>

// ============================================================================
// GAT 2-layer forward, exact-math O(n log n) reformulation.
// softmax_j(LeakyReLU(s_i + d_j)) @ V via sorted-d tables:
//   P = forward prefix of e^{d-dmax}*v ; Q = reverse suffix of e^{0.2(d-dmax)}*v
// R5: keys-only 20-bit radix sort (index packed in low 12 bits),
//     float4-x register-tiled GEMM @256thr, scanB folded into scanC.
// ============================================================================

#define NB 4
#define NN 4096
#define EPSN 1e-5f
#define NT 32      // scan tiles per chain
#define TS 128     // scan tile size (NT*TS == NN)
#define NSLAB 16

template<int L> struct LP {
  static constexpr int CIN  = (L == 0) ? 64 : 128;
  static constexpr int H    = (L == 0) ? 4 : 1;
  static constexpr int K    = (L == 0) ? 32 : 64;
  static constexpr int COUT = H * K;
};

// ---------------- scratch (device globals; no allocation allowed) ----------
__device__ float  g_part0[NB * NSLAB * 64 * 2];
__device__ float  g_part1[NB * NSLAB * 128 * 2];
__device__ float  g_w0p[NB * 64 * 128], g_t0[NB * 128];
__device__ float  g_w1p[NB * 128 * 64], g_t1[NB * 64];
__device__ float  g_feat0[16 * NN * 32];
__device__ float  g_feat1[4 * NN * 64];
__device__ float  g_ssrc0[16 * NN], g_sdst0[16 * NN];
__device__ float  g_ssrc1[4 * NN],  g_sdst1[4 * NN];
__device__ float  g_sortd0[16 * NN];
__device__ int    g_perm0[16 * NN];
__device__ float  g_sortd1[4 * NN];
__device__ int    g_perm1[4 * NN];
__device__ float  g_wP0[16 * NN], g_wQ0[16 * NN];
__device__ float  g_wP1[4 * NN],  g_wQ1[4 * NN];
__device__ float  g_ts0[32 * NT * 33];
__device__ float  g_ts1[8 * NT * 65];
__device__ float  g_pref0[(size_t)16 * 2 * (NN + 1) * 33];
__device__ float  g_pref1[(size_t)4  * 2 * (NN + 1) * 65];
__device__ float  g_cat[(size_t)NB * NN * 128];

// ---------------- instance-norm stats: coalesced slab partials -------------
template<int L>
__global__ void stats_part_kernel(const float* __restrict__ xext) {
  constexpr int C = LP<L>::CIN;
  constexpr int RP = 256 / C;
  const float* x = (L == 0) ? xext : g_cat;
  float* part = (L == 0) ? g_part0 : g_part1;
  int b = blockIdx.x, slab = blockIdx.y;
  int c = threadIdx.x % C, rr = threadIdx.x / C;
  const float* p = x + ((size_t)b * NN + (size_t)slab * 256) * C;
  float s = 0.f, s2 = 0.f;
  for (int i = rr; i < 256; i += RP) {
    float v = p[(size_t)i * C + c];
    s += v; s2 = fmaf(v, v, s2);
  }
  __shared__ float sh[256], sh2[256];
  sh[threadIdx.x] = s; sh2[threadIdx.x] = s2;
  __syncthreads();
  if (rr == 0) {
    float S = s, S2 = s2;
    #pragma unroll
    for (int j = 1; j < RP; ++j) { S += sh[j * C + c]; S2 += sh2[j * C + c]; }
    size_t o = (((size_t)b * NSLAB + slab) * C + c) * 2;
    part[o] = S; part[o + 1] = S2;
  }
}

// ---------------- combine stats + fold instance-norm into weights ----------
template<int L>
__global__ void fold_kernel(const float* __restrict__ w) {
  constexpr int CIN = LP<L>::CIN, K = LP<L>::K, COUT = LP<L>::COUT;
  const float* part = (L == 0) ? g_part0 : g_part1;
  float* wp = (L == 0) ? g_w0p : g_w1p;
  float* tv = (L == 0) ? g_t0 : g_t1;
  __shared__ float mu[CIN], rs[CIN];
  int b = blockIdx.x, tid = threadIdx.x;
  if (tid < CIN) {
    double S = 0.0, S2 = 0.0;
    for (int slab = 0; slab < NSLAB; ++slab) {
      size_t o = (((size_t)b * NSLAB + slab) * CIN + tid) * 2;
      S += (double)part[o]; S2 += (double)part[o + 1];
    }
    double mean = S / NN;
    double var = S2 / NN - mean * mean;
    mu[tid] = (float)mean;
    rs[tid] = (float)(1.0 / sqrt(var + (double)EPSN));
  }
  __syncthreads();
  if (tid < COUT) {
    int h = tid / K, k = tid % K;
    float acc = 0.f;
    for (int c = 0; c < CIN; ++c) {
      float wv  = w[((size_t)h * CIN + c) * K + k];
      float wpv = wv * rs[c];
      wp[((size_t)b * CIN + c) * COUT + tid] = wpv;
      acc = fmaf(mu[c], wpv, acc);
    }
    tv[b * COUT + tid] = acc;
  }
}

// ---------------- GEMM (float4-x register-tiled) + fused s_src/s_dst -------
// 256 threads. ROWS rows per block; thread: RT rows x 4 cols.
template<int L>
__global__ void gemm_kernel(const float* __restrict__ xext,
                            const float* __restrict__ a_src,
                            const float* __restrict__ a_dst) {
  constexpr int CIN = LP<L>::CIN, H = LP<L>::H, K = LP<L>::K, COUT = LP<L>::COUT;
  constexpr int ROWS = (L == 0) ? 64 : 32;
  constexpr int NC = COUT / 4;      // 32 / 16 col-threads
  constexpr int NR = 256 / NC;      // 8 / 16 row-threads
  constexpr int RT = ROWS / NR;     // 8 / 2 rows per thread
  constexpr int G  = NC / H;        // 8 / 16 lanes per head group
  const float* x  = (L == 0) ? xext : g_cat;
  const float* wp = (L == 0) ? g_w0p : g_w1p;
  const float* tv = (L == 0) ? g_t0 : g_t1;
  float* feat = (L == 0) ? g_feat0 : g_feat1;
  float* ssrc = (L == 0) ? g_ssrc0 : g_ssrc1;
  float* sdst = (L == 0) ? g_sdst0 : g_sdst1;
  __shared__ float ws[CIN * COUT];
  __shared__ float xs[ROWS * CIN];
  int b = blockIdx.x, bt = blockIdx.y;
  int tid = threadIdx.x;
  const float4* wsrc = (const float4*)(wp + (size_t)b * CIN * COUT);
  for (int i = tid; i < CIN * COUT / 4; i += 256) ((float4*)ws)[i] = wsrc[i];
  const float4* xsrc = (const float4*)(x + ((size_t)b * NN + (size_t)bt * ROWS) * CIN);
  for (int i = tid; i < ROWS * CIN / 4; i += 256) ((float4*)xs)[i] = xsrc[i];
  __syncthreads();
  int tc = tid % NC, tr = tid / NC;
  int col0 = tc * 4, r0 = tr * RT;
  float4 tv4 = *(const float4*)(tv + b * COUT + col0);
  float acc[RT][4];
  #pragma unroll
  for (int i = 0; i < RT; ++i) {
    acc[i][0] = -tv4.x; acc[i][1] = -tv4.y; acc[i][2] = -tv4.z; acc[i][3] = -tv4.w;
  }
  const float4* wsv = (const float4*)ws;
  const float4* xsv = (const float4*)xs;
  #pragma unroll 4
  for (int c = 0; c < CIN; c += 4) {
    float4 w0 = wsv[(c + 0) * NC + tc];
    float4 w1 = wsv[(c + 1) * NC + tc];
    float4 w2 = wsv[(c + 2) * NC + tc];
    float4 w3 = wsv[(c + 3) * NC + tc];
    #pragma unroll
    for (int i = 0; i < RT; ++i) {
      float4 xv = xsv[(r0 + i) * (CIN / 4) + (c >> 2)];
      acc[i][0] = fmaf(xv.x, w0.x, acc[i][0]);
      acc[i][1] = fmaf(xv.x, w0.y, acc[i][1]);
      acc[i][2] = fmaf(xv.x, w0.z, acc[i][2]);
      acc[i][3] = fmaf(xv.x, w0.w, acc[i][3]);
      acc[i][0] = fmaf(xv.y, w1.x, acc[i][0]);
      acc[i][1] = fmaf(xv.y, w1.y, acc[i][1]);
      acc[i][2] = fmaf(xv.y, w1.z, acc[i][2]);
      acc[i][3] = fmaf(xv.y, w1.w, acc[i][3]);
      acc[i][0] = fmaf(xv.z, w2.x, acc[i][0]);
      acc[i][1] = fmaf(xv.z, w2.y, acc[i][1]);
      acc[i][2] = fmaf(xv.z, w2.z, acc[i][2]);
      acc[i][3] = fmaf(xv.z, w2.w, acc[i][3]);
      acc[i][0] = fmaf(xv.w, w3.x, acc[i][0]);
      acc[i][1] = fmaf(xv.w, w3.y, acc[i][1]);
      acc[i][2] = fmaf(xv.w, w3.z, acc[i][2]);
      acc[i][3] = fmaf(xv.w, w3.w, acc[i][3]);
    }
  }
  int h = col0 / K, k0 = col0 % K;
  float4 as4 = *(const float4*)(a_src + col0);
  float4 ad4 = *(const float4*)(a_dst + col0);
  int nbase = bt * ROWS + r0;
  float* fo = feat + (((size_t)b * H + h) * NN + nbase) * K + k0;
  size_t sbase = ((size_t)b * H + h) * NN + nbase;
  #pragma unroll
  for (int i = 0; i < RT; ++i) {
    *(float4*)(fo + (size_t)i * K) = make_float4(acc[i][0], acc[i][1], acc[i][2], acc[i][3]);
    float s1 = acc[i][0] * as4.x + acc[i][1] * as4.y + acc[i][2] * as4.z + acc[i][3] * as4.w;
    float s2 = acc[i][0] * ad4.x + acc[i][1] * ad4.y + acc[i][2] * ad4.z + acc[i][3] * ad4.w;
    #pragma unroll
    for (int off = 1; off < G; off <<= 1) {
      s1 += __shfl_xor_sync(0xffffffffu, s1, off);
      s2 += __shfl_xor_sync(0xffffffffu, s2, off);
    }
    if ((tc & (G - 1)) == 0) {
      ssrc[sbase + i] = s1;
      sdst[sbase + i] = s2;
    }
  }
}

// ---------------- keys-only 20-bit radix sort + wP/wQ weights --------------
// key = (monotone(float) & 0xFFFFF000) | index.  Sorted on bits [12,32).
// Boundary quantization error ~2^-11 relative — negligible through LeakyReLU.
template<int L>
__global__ void sort_kernel() {
  constexpr int BT = 512, IPT = NN / BT;  // 8
  const float* sdstA = (L == 0) ? g_sdst0 : g_sdst1;
  float* sortd = (L == 0) ? g_sortd0 : g_sortd1;
  int*   perm  = (L == 0) ? g_perm0 : g_perm1;
  float* wP = (L == 0) ? g_wP0 : g_wP1;
  float* wQ = (L == 0) ? g_wQ0 : g_wQ1;
  using BRS = cub::BlockRadixSort<unsigned, BT, IPT>;
  __shared__ typename BRS::TempStorage ts;
  __shared__ float sdmax;
  int bh = blockIdx.x;
  const float* src = sdstA + (size_t)bh * NN;
  unsigned keys[IPT];
  int base = threadIdx.x * IPT;
  #pragma unroll
  for (int i = 0; i < IPT; ++i) {
    unsigned u = __float_as_uint(src[base + i]);
    u ^= (u & 0x80000000u) ? 0xFFFFFFFFu : 0x80000000u;
    keys[i] = (u & 0xFFFFF000u) | (unsigned)(base + i);
  }
  BRS(ts).SortDescending(keys, 12, 32);
  if (threadIdx.x == 0) sdmax = src[keys[0] & 0xFFFu];
  __syncthreads();
  float dmax = sdmax;
  #pragma unroll
  for (int i = 0; i < IPT; ++i) {
    int p = (int)(keys[i] & 0xFFFu);
    float d = src[p];
    size_t o = (size_t)bh * NN + base + i;
    sortd[o] = d;
    perm[o]  = p;
    wP[o] = expf(d - dmax);
    wQ[o] = expf(0.2f * (d - dmax));
  }
}

// ---------------- scan pass A: per-tile sums, both branches ----------------
template<int L>
__global__ void scanA_kernel() {
  constexpr int K = LP<L>::K;
  constexpr int RS = 128 / K;
  const float* feat = (L == 0) ? g_feat0 : g_feat1;
  const int*   perm = (L == 0) ? g_perm0 : g_perm1;
  const float* wPg = (L == 0) ? g_wP0 : g_wP1;
  const float* wQg = (L == 0) ? g_wQ0 : g_wQ1;
  float* tsum = (L == 0) ? g_ts0 : g_ts1;
  int bh = blockIdx.x, tile = blockIdx.y, pos0 = tile * TS;
  int k = threadIdx.x % K, r = threadIdx.x / K;
  const float* fe = feat + (size_t)bh * NN * K;
  const int*   pm = perm + (size_t)bh * NN + pos0;
  const float* wp = wPg + (size_t)bh * NN + pos0;
  const float* wq = wQg + (size_t)bh * NN + pos0;
  float aP = 0.f, aQ = 0.f;
  for (int i = r; i < TS; i += RS) {
    int p = pm[i];
    float v = fe[(size_t)p * K + k];
    aP = fmaf(wp[i], v, aP);
    aQ = fmaf(wq[i], v, aQ);
  }
  __shared__ float redP[128], redQ[128];
  redP[threadIdx.x] = aP; redQ[threadIdx.x] = aQ;
  __syncthreads();
  size_t tbP = ((size_t)(bh * 2)     * NT + tile) * (K + 1);
  size_t tbQ = ((size_t)(bh * 2 + 1) * NT + tile) * (K + 1);
  if (r == 0) {
    float sP = aP, sQ = aQ;
    #pragma unroll
    for (int j = 1; j < RS; ++j) { sP += redP[j * K + k]; sQ += redQ[j * K + k]; }
    tsum[tbP + k] = sP;
    tsum[tbQ + k] = sQ;
  }
  if (threadIdx.x < 32) {
    float wa = 0.f, wb = 0.f;
    #pragma unroll
    for (int i = 0; i < TS / 32; ++i) {
      wa += wp[threadIdx.x + 32 * i];
      wb += wq[threadIdx.x + 32 * i];
    }
    #pragma unroll
    for (int o = 16; o; o >>= 1) {
      wa += __shfl_down_sync(0xffffffffu, wa, o);
      wb += __shfl_down_sync(0xffffffffu, wb, o);
    }
    if (threadIdx.x == 0) { tsum[tbP + K] = wa; tsum[tbQ + K] = wb; }
  }
}

// ---------------- scan pass C: offsets from tsum + tile-local scans --------
// 256 threads: tid in [0,K] -> P (fwd exclusive); tid-128 in [0,K] -> Q (rev
// inclusive = suffix). Chain offsets recomputed from tsum (scanB folded in).
template<int L>
__global__ void scanC_kernel() {
  constexpr int K = LP<L>::K;
  const float* feat = (L == 0) ? g_feat0 : g_feat1;
  const int*   perm = (L == 0) ? g_perm0 : g_perm1;
  const float* wPg = (L == 0) ? g_wP0 : g_wP1;
  const float* wQg = (L == 0) ? g_wQ0 : g_wQ1;
  const float* tsum = (L == 0) ? g_ts0 : g_ts1;
  float* pref = (L == 0) ? g_pref0 : g_pref1;
  __shared__ float vs[TS * K];
  __shared__ float wPs[TS], wQs[TS];
  __shared__ int pm[TS];
  int bh = blockIdx.x, tile = blockIdx.y, pos0 = tile * TS;
  int tid = threadIdx.x;
  if (tid < TS) {
    size_t o = (size_t)bh * NN + pos0 + tid;
    pm[tid] = perm[o];
    wPs[tid] = wPg[o];
    wQs[tid] = wQg[o];
  }
  __syncthreads();
  const float* fe = feat + (size_t)bh * NN * K;
  for (int e = tid; e < TS * K; e += 256) {
    int i = e / K, k = e % K;
    vs[e] = fe[(size_t)pm[i] * K + k];
  }
  __syncthreads();
  if (tid <= K) {
    int d = tid;
    size_t cb = (size_t)(bh * 2) * NT;
    float run = 0.f;
    for (int tt = 0; tt < tile; ++tt) run += tsum[(cb + tt) * (K + 1) + d];
    float* outP = pref + ((size_t)(bh * 2) * (NN + 1) + pos0) * (K + 1) + d;
    if (d < K) {
      for (int i = 0; i < TS; ++i) {
        outP[(size_t)i * (K + 1)] = run;
        run = fmaf(wPs[i], vs[i * K + d], run);
      }
    } else {
      for (int i = 0; i < TS; ++i) {
        outP[(size_t)i * (K + 1)] = run;
        run += wPs[i];
      }
    }
    if (tile == NT - 1)
      pref[((size_t)(bh * 2) * (NN + 1) + NN) * (K + 1) + d] = run;  // P total
  } else if (tid >= 128 && tid <= 128 + K) {
    int d = tid - 128;
    size_t cb = (size_t)(bh * 2 + 1) * NT;
    float run = 0.f;
    for (int tt = tile + 1; tt < NT; ++tt) run += tsum[(cb + tt) * (K + 1) + d];
    float* outQ = pref + ((size_t)(bh * 2 + 1) * (NN + 1) + pos0) * (K + 1) + d;
    if (d < K) {
      for (int i = TS - 1; i >= 0; --i) {
        run = fmaf(wQs[i], vs[i * K + d], run);
        outQ[(size_t)i * (K + 1)] = run;
      }
    } else {
      for (int i = TS - 1; i >= 0; --i) {
        run += wQs[i];
        outQ[(size_t)i * (K + 1)] = run;
      }
    }
    if (tile == NT - 1)
      pref[((size_t)(bh * 2 + 1) * (NN + 1) + NN) * (K + 1) + d] = 0.f;  // Q suffix at NN
  }
}

// ---------------- per-row combine: parallel search + prefix gather ----------
template<int L>
__global__ void rows_kernel(const float* __restrict__ bias,
                            float* __restrict__ outext) {
  constexpr int K = LP<L>::K, H = LP<L>::H;
  constexpr bool ELU = (L == 0);
  constexpr int RPB = 128;
  const float* ssrc  = (L == 0) ? g_ssrc0 : g_ssrc1;
  const float* sortd = (L == 0) ? g_sortd0 : g_sortd1;
  const float* pref  = (L == 0) ? g_pref0 : g_pref1;
  float* out = (L == 0) ? g_cat : outext;

  int bh = blockIdx.x;
  __shared__ float sd[NN];
  __shared__ int   ms[RPB];
  __shared__ float al[RPB], be[RPB];
  __shared__ float bs[K];
  for (int i = threadIdx.x; i < NN; i += 256) sd[i] = sortd[(size_t)bh * NN + i];
  const float* prefP = pref + (size_t)(bh * 2) * (NN + 1) * (K + 1);
  const float* prefQ = prefP + (size_t)(NN + 1) * (K + 1);
  if (threadIdx.x < K) bs[threadIdx.x] = bias[threadIdx.x];
  __syncthreads();

  float dmax = sd[0];
  int row0 = blockIdx.y * RPB;

  if (threadIdx.x < RPB) {
    int r = row0 + threadIdx.x;
    float s = ssrc[(size_t)bh * NN + r];
    float T = s + dmax;
    if (T > 0.f) { al[threadIdx.x] = 1.f; be[threadIdx.x] = expf(-0.8f * T); }
    else         { al[threadIdx.x] = expf(0.8f * T); be[threadIdx.x] = 1.f; }
    float thr = -s;
    int lo = 0, hi = NN;
    while (lo < hi) {
      int mid = (lo + hi) >> 1;
      if (sd[mid] > thr) lo = mid + 1; else hi = mid;
    }
    ms[threadIdx.x] = lo;
  }
  __syncthreads();

  int warp = threadIdx.x >> 5, lane = threadIdx.x & 31;
  int b = bh / H, h = bh % H;
  for (int rr = warp; rr < RPB; rr += 8) {
    int r = row0 + rr;
    int m = ms[rr];
    float alpha = al[rr], beta = be[rr];
    const float* pP = prefP + (size_t)m * (K + 1);
    const float* pQ = prefQ + (size_t)m * (K + 1);
    float den = alpha * pP[K] + beta * pQ[K];
    float inv = 1.f / den;
    #pragma unroll
    for (int k = lane; k < K; k += 32) {
      float num = alpha * pP[k] + beta * pQ[k];
      float v = num * inv + bs[k];
      size_t oi = ((size_t)b * NN + r) * (size_t)(H * K) + (size_t)h * K + k;
      if (ELU) out[oi] = (v > 0.f) ? v : (expf(v) - 1.f);
      else     out[oi] = v;
    }
  }
}

// ---------------- launch ----------------------------------------------------
extern "C" void kernel_launch(void* const* d_in, const int* in_sizes, int n_in,
                              void* d_out, int out_size) {
  (void)in_sizes; (void)n_in; (void)out_size;
  const float* x      = (const float*)d_in[0];
  const float* w0     = (const float*)d_in[1];
  const float* a_src0 = (const float*)d_in[2];
  const float* a_dst0 = (const float*)d_in[3];
  const float* b0     = (const float*)d_in[4];
  const float* w1     = (const float*)d_in[5];
  const float* a_src1 = (const float*)d_in[6];
  const float* a_dst1 = (const float*)d_in[7];
  const float* b1     = (const float*)d_in[8];
  float* out = (float*)d_out;

  // ---- layer 0 ----
  stats_part_kernel<0><<<dim3(NB, NSLAB), 256>>>(x);
  fold_kernel<0><<<NB, 128>>>(w0);
  gemm_kernel<0><<<dim3(NB, NN / 64), 256>>>(x, a_src0, a_dst0);
  sort_kernel<0><<<16, 512>>>();
  scanA_kernel<0><<<dim3(16, NT), 128>>>();
  scanC_kernel<0><<<dim3(16, NT), 256>>>();
  rows_kernel<0><<<dim3(16, NN / 128), 256>>>(b0, nullptr);

  // ---- layer 1 ----
  stats_part_kernel<1><<<dim3(NB, NSLAB), 256>>>(nullptr);
  fold_kernel<1><<<NB, 128>>>(w1);
  gemm_kernel<1><<<dim3(NB, NN / 32), 256>>>(nullptr, a_src1, a_dst1);
  sort_kernel<1><<<4, 512>>>();
  scanA_kernel<1><<<dim3(4, NT), 128>>>();
  scanC_kernel<1><<<dim3(4, NT), 256>>>();
  rows_kernel<1><<<dim3(4, NN / 128), 256>>>(b1, out);
}

// round 6
// speedup vs baseline: 2.0178x; 1.1155x over previous
#include <cuda_runtime.h>
#include <math.h>

// ============================================================================
// GAT 2-layer forward, exact-math O(n log n) reformulation.
// softmax_j(LeakyReLU(s_i + d_j)) @ V via sorted-d tables:
//   P = forward prefix of e^{d-dmax}*v ; Q = reverse suffix of e^{0.2(d-dmax)}*v
// R6: single-pass smem counting sort (4096 linear buckets) replaces radix.
// ============================================================================

#define NB 4
#define NN 4096
#define EPSN 1e-5f
#define NT 32      // scan tiles per chain
#define TS 128     // scan tile size (NT*TS == NN)
#define NSLAB 16

template<int L> struct LP {
  static constexpr int CIN  = (L == 0) ? 64 : 128;
  static constexpr int H    = (L == 0) ? 4 : 1;
  static constexpr int K    = (L == 0) ? 32 : 64;
  static constexpr int COUT = H * K;
};

// ---------------- scratch (device globals; no allocation allowed) ----------
__device__ float  g_part0[NB * NSLAB * 64 * 2];
__device__ float  g_part1[NB * NSLAB * 128 * 2];
__device__ float  g_w0p[NB * 64 * 128], g_t0[NB * 128];
__device__ float  g_w1p[NB * 128 * 64], g_t1[NB * 64];
__device__ float  g_feat0[16 * NN * 32];
__device__ float  g_feat1[4 * NN * 64];
__device__ float  g_ssrc0[16 * NN], g_sdst0[16 * NN];
__device__ float  g_ssrc1[4 * NN],  g_sdst1[4 * NN];
__device__ float  g_sortd0[16 * NN];
__device__ int    g_perm0[16 * NN];
__device__ float  g_sortd1[4 * NN];
__device__ int    g_perm1[4 * NN];
__device__ float  g_dmax0[16], g_dmax1[4];
__device__ float  g_wP0[16 * NN], g_wQ0[16 * NN];
__device__ float  g_wP1[4 * NN],  g_wQ1[4 * NN];
__device__ float  g_ts0[32 * NT * 33];
__device__ float  g_ts1[8 * NT * 65];
__device__ float  g_pref0[(size_t)16 * 2 * (NN + 1) * 33];
__device__ float  g_pref1[(size_t)4  * 2 * (NN + 1) * 65];
__device__ float  g_cat[(size_t)NB * NN * 128];

// ---------------- instance-norm stats: coalesced slab partials -------------
template<int L>
__global__ void stats_part_kernel(const float* __restrict__ xext) {
  constexpr int C = LP<L>::CIN;
  constexpr int RP = 256 / C;
  const float* x = (L == 0) ? xext : g_cat;
  float* part = (L == 0) ? g_part0 : g_part1;
  int b = blockIdx.x, slab = blockIdx.y;
  int c = threadIdx.x % C, rr = threadIdx.x / C;
  const float* p = x + ((size_t)b * NN + (size_t)slab * 256) * C;
  float s = 0.f, s2 = 0.f;
  for (int i = rr; i < 256; i += RP) {
    float v = p[(size_t)i * C + c];
    s += v; s2 = fmaf(v, v, s2);
  }
  __shared__ float sh[256], sh2[256];
  sh[threadIdx.x] = s; sh2[threadIdx.x] = s2;
  __syncthreads();
  if (rr == 0) {
    float S = s, S2 = s2;
    #pragma unroll
    for (int j = 1; j < RP; ++j) { S += sh[j * C + c]; S2 += sh2[j * C + c]; }
    size_t o = (((size_t)b * NSLAB + slab) * C + c) * 2;
    part[o] = S; part[o + 1] = S2;
  }
}

// ---------------- combine stats + fold instance-norm into weights ----------
template<int L>
__global__ void fold_kernel(const float* __restrict__ w) {
  constexpr int CIN = LP<L>::CIN, K = LP<L>::K, COUT = LP<L>::COUT;
  const float* part = (L == 0) ? g_part0 : g_part1;
  float* wp = (L == 0) ? g_w0p : g_w1p;
  float* tv = (L == 0) ? g_t0 : g_t1;
  __shared__ float mu[CIN], rs[CIN];
  int b = blockIdx.x, tid = threadIdx.x;
  if (tid < CIN) {
    double S = 0.0, S2 = 0.0;
    for (int slab = 0; slab < NSLAB; ++slab) {
      size_t o = (((size_t)b * NSLAB + slab) * CIN + tid) * 2;
      S += (double)part[o]; S2 += (double)part[o + 1];
    }
    double mean = S / NN;
    double var = S2 / NN - mean * mean;
    mu[tid] = (float)mean;
    rs[tid] = (float)(1.0 / sqrt(var + (double)EPSN));
  }
  __syncthreads();
  if (tid < COUT) {
    int h = tid / K, k = tid % K;
    float acc = 0.f;
    for (int c = 0; c < CIN; ++c) {
      float wv  = w[((size_t)h * CIN + c) * K + k];
      float wpv = wv * rs[c];
      wp[((size_t)b * CIN + c) * COUT + tid] = wpv;
      acc = fmaf(mu[c], wpv, acc);
    }
    tv[b * COUT + tid] = acc;
  }
}

// ---------------- GEMM (float4-x register-tiled) + fused s_src/s_dst -------
template<int L>
__global__ void gemm_kernel(const float* __restrict__ xext,
                            const float* __restrict__ a_src,
                            const float* __restrict__ a_dst) {
  constexpr int CIN = LP<L>::CIN, H = LP<L>::H, K = LP<L>::K, COUT = LP<L>::COUT;
  constexpr int ROWS = (L == 0) ? 64 : 32;
  constexpr int NC = COUT / 4;
  constexpr int NR = 256 / NC;
  constexpr int RT = ROWS / NR;
  constexpr int G  = NC / H;
  const float* x  = (L == 0) ? xext : g_cat;
  const float* wp = (L == 0) ? g_w0p : g_w1p;
  const float* tv = (L == 0) ? g_t0 : g_t1;
  float* feat = (L == 0) ? g_feat0 : g_feat1;
  float* ssrc = (L == 0) ? g_ssrc0 : g_ssrc1;
  float* sdst = (L == 0) ? g_sdst0 : g_sdst1;
  __shared__ float ws[CIN * COUT];
  __shared__ float xs[ROWS * CIN];
  int b = blockIdx.x, bt = blockIdx.y;
  int tid = threadIdx.x;
  const float4* wsrc = (const float4*)(wp + (size_t)b * CIN * COUT);
  for (int i = tid; i < CIN * COUT / 4; i += 256) ((float4*)ws)[i] = wsrc[i];
  const float4* xsrc = (const float4*)(x + ((size_t)b * NN + (size_t)bt * ROWS) * CIN);
  for (int i = tid; i < ROWS * CIN / 4; i += 256) ((float4*)xs)[i] = xsrc[i];
  __syncthreads();
  int tc = tid % NC, tr = tid / NC;
  int col0 = tc * 4, r0 = tr * RT;
  float4 tv4 = *(const float4*)(tv + b * COUT + col0);
  float acc[RT][4];
  #pragma unroll
  for (int i = 0; i < RT; ++i) {
    acc[i][0] = -tv4.x; acc[i][1] = -tv4.y; acc[i][2] = -tv4.z; acc[i][3] = -tv4.w;
  }
  const float4* wsv = (const float4*)ws;
  const float4* xsv = (const float4*)xs;
  #pragma unroll 4
  for (int c = 0; c < CIN; c += 4) {
    float4 w0 = wsv[(c + 0) * NC + tc];
    float4 w1 = wsv[(c + 1) * NC + tc];
    float4 w2 = wsv[(c + 2) * NC + tc];
    float4 w3 = wsv[(c + 3) * NC + tc];
    #pragma unroll
    for (int i = 0; i < RT; ++i) {
      float4 xv = xsv[(r0 + i) * (CIN / 4) + (c >> 2)];
      acc[i][0] = fmaf(xv.x, w0.x, acc[i][0]);
      acc[i][1] = fmaf(xv.x, w0.y, acc[i][1]);
      acc[i][2] = fmaf(xv.x, w0.z, acc[i][2]);
      acc[i][3] = fmaf(xv.x, w0.w, acc[i][3]);
      acc[i][0] = fmaf(xv.y, w1.x, acc[i][0]);
      acc[i][1] = fmaf(xv.y, w1.y, acc[i][1]);
      acc[i][2] = fmaf(xv.y, w1.z, acc[i][2]);
      acc[i][3] = fmaf(xv.y, w1.w, acc[i][3]);
      acc[i][0] = fmaf(xv.z, w2.x, acc[i][0]);
      acc[i][1] = fmaf(xv.z, w2.y, acc[i][1]);
      acc[i][2] = fmaf(xv.z, w2.z, acc[i][2]);
      acc[i][3] = fmaf(xv.z, w2.w, acc[i][3]);
      acc[i][0] = fmaf(xv.w, w3.x, acc[i][0]);
      acc[i][1] = fmaf(xv.w, w3.y, acc[i][1]);
      acc[i][2] = fmaf(xv.w, w3.z, acc[i][2]);
      acc[i][3] = fmaf(xv.w, w3.w, acc[i][3]);
    }
  }
  int h = col0 / K, k0 = col0 % K;
  float4 as4 = *(const float4*)(a_src + col0);
  float4 ad4 = *(const float4*)(a_dst + col0);
  int nbase = bt * ROWS + r0;
  float* fo = feat + (((size_t)b * H + h) * NN + nbase) * K + k0;
  size_t sbase = ((size_t)b * H + h) * NN + nbase;
  #pragma unroll
  for (int i = 0; i < RT; ++i) {
    *(float4*)(fo + (size_t)i * K) = make_float4(acc[i][0], acc[i][1], acc[i][2], acc[i][3]);
    float s1 = acc[i][0] * as4.x + acc[i][1] * as4.y + acc[i][2] * as4.z + acc[i][3] * as4.w;
    float s2 = acc[i][0] * ad4.x + acc[i][1] * ad4.y + acc[i][2] * ad4.z + acc[i][3] * ad4.w;
    #pragma unroll
    for (int off = 1; off < G; off <<= 1) {
      s1 += __shfl_xor_sync(0xffffffffu, s1, off);
      s2 += __shfl_xor_sync(0xffffffffu, s2, off);
    }
    if ((tc & (G - 1)) == 0) {
      ssrc[sbase + i] = s1;
      sdst[sbase + i] = s2;
    }
  }
}

// ---------------- single-pass counting sort (4096 buckets) + weights -------
// Descending by d. Within-bucket order arbitrary (±range/4096 in d) — the
// boundary-quantization error this admits is ~e^{0.8*0.005} per boundary
// element, negligible (validated: 20-bit key quantization moved rel_err 0).
template<int L>
__global__ void sort_kernel() {
  constexpr int BT = 512, IPT = NN / BT;  // 8
  const float* sdstA = (L == 0) ? g_sdst0 : g_sdst1;
  float* sortd = (L == 0) ? g_sortd0 : g_sortd1;
  int*   perm  = (L == 0) ? g_perm0 : g_perm1;
  float* wP = (L == 0) ? g_wP0 : g_wP1;
  float* wQ = (L == 0) ? g_wQ0 : g_wQ1;
  float* dmaxA = (L == 0) ? g_dmax0 : g_dmax1;

  __shared__ int   cnt[NN];       // 16 KB: histogram -> offsets
  __shared__ int   perm_s[NN];    // 16 KB: rank -> original index
  __shared__ float wred[32];
  __shared__ int   wsum[16];
  __shared__ float s_mn, s_mx;

  int bh = blockIdx.x;
  int tid = threadIdx.x, lane = tid & 31, wid = tid >> 5;
  const float* src = sdstA + (size_t)bh * NN;

  float d[IPT];
  int base = tid * IPT;
  #pragma unroll
  for (int i = 0; i < IPT; ++i) d[i] = src[base + i];

  // exact block min/max
  float mn = d[0], mx = d[0];
  #pragma unroll
  for (int i = 1; i < IPT; ++i) { mn = fminf(mn, d[i]); mx = fmaxf(mx, d[i]); }
  #pragma unroll
  for (int o = 16; o; o >>= 1) {
    mn = fminf(mn, __shfl_xor_sync(0xffffffffu, mn, o));
    mx = fmaxf(mx, __shfl_xor_sync(0xffffffffu, mx, o));
  }
  if (lane == 0) { wred[wid] = mn; wred[wid + 16] = mx; }
  for (int i = tid; i < NN; i += BT) cnt[i] = 0;
  __syncthreads();
  if (tid == 0) {
    float m1 = wred[0], m2 = wred[16];
    #pragma unroll
    for (int i = 1; i < 16; ++i) { m1 = fminf(m1, wred[i]); m2 = fmaxf(m2, wred[i + 16]); }
    s_mn = m1; s_mx = m2;
    dmaxA[bh] = m2;
  }
  __syncthreads();
  float dmax = s_mx;
  float scale = (float)(NN - 1) / fmaxf(s_mx - s_mn, 1e-30f);

  // histogram
  int bkt[IPT];
  #pragma unroll
  for (int i = 0; i < IPT; ++i) {
    int bb = (int)((dmax - d[i]) * scale);
    bkt[i] = min(max(bb, 0), NN - 1);
    atomicAdd(&cnt[bkt[i]], 1);
  }
  __syncthreads();

  // exclusive scan of cnt[0..NN): 8 per thread + hierarchical block scan
  int base8 = tid * 8;
  int c8[8]; int tsum = 0;
  #pragma unroll
  for (int j = 0; j < 8; ++j) { c8[j] = cnt[base8 + j]; tsum += c8[j]; }
  int pre = tsum;
  #pragma unroll
  for (int o = 1; o < 32; o <<= 1) {
    int nv = __shfl_up_sync(0xffffffffu, pre, o);
    if (lane >= o) pre += nv;
  }
  pre -= tsum;  // exclusive within warp
  if (lane == 31) wsum[wid] = pre + tsum;
  __syncthreads();
  if (tid < 16) {
    int v = wsum[tid];
    int iv = v;
    #pragma unroll
    for (int o = 1; o < 16; o <<= 1) {
      int nv = __shfl_up_sync(0xffffu, iv, o);
      if (tid >= o) iv += nv;
    }
    wsum[tid] = iv - v;  // exclusive warp offsets
  }
  __syncthreads();
  int run = wsum[wid] + pre;
  #pragma unroll
  for (int j = 0; j < 8; ++j) { cnt[base8 + j] = run; run += c8[j]; }
  __syncthreads();

  // scatter ranks into smem
  #pragma unroll
  for (int i = 0; i < IPT; ++i) {
    int r = atomicAdd(&cnt[bkt[i]], 1);
    perm_s[r] = base + i;
  }
  __syncthreads();

  // coalesced output pass (+ exp weights)
  for (int r = tid; r < NN; r += BT) {
    int p = perm_s[r];
    float dv = src[p];
    size_t o = (size_t)bh * NN + r;
    sortd[o] = dv;
    perm[o]  = p;
    float e = dv - dmax;
    wP[o] = expf(e);
    wQ[o] = expf(0.2f * e);
  }
}

// ---------------- scan pass A: per-tile sums, both branches ----------------
template<int L>
__global__ void scanA_kernel() {
  constexpr int K = LP<L>::K;
  constexpr int RS = 128 / K;
  const float* feat = (L == 0) ? g_feat0 : g_feat1;
  const int*   perm = (L == 0) ? g_perm0 : g_perm1;
  const float* wPg = (L == 0) ? g_wP0 : g_wP1;
  const float* wQg = (L == 0) ? g_wQ0 : g_wQ1;
  float* tsum = (L == 0) ? g_ts0 : g_ts1;
  int bh = blockIdx.x, tile = blockIdx.y, pos0 = tile * TS;
  int k = threadIdx.x % K, r = threadIdx.x / K;
  const float* fe = feat + (size_t)bh * NN * K;
  const int*   pm = perm + (size_t)bh * NN + pos0;
  const float* wp = wPg + (size_t)bh * NN + pos0;
  const float* wq = wQg + (size_t)bh * NN + pos0;
  float aP = 0.f, aQ = 0.f;
  for (int i = r; i < TS; i += RS) {
    int p = pm[i];
    float v = fe[(size_t)p * K + k];
    aP = fmaf(wp[i], v, aP);
    aQ = fmaf(wq[i], v, aQ);
  }
  __shared__ float redP[128], redQ[128];
  redP[threadIdx.x] = aP; redQ[threadIdx.x] = aQ;
  __syncthreads();
  size_t tbP = ((size_t)(bh * 2)     * NT + tile) * (K + 1);
  size_t tbQ = ((size_t)(bh * 2 + 1) * NT + tile) * (K + 1);
  if (r == 0) {
    float sP = aP, sQ = aQ;
    #pragma unroll
    for (int j = 1; j < RS; ++j) { sP += redP[j * K + k]; sQ += redQ[j * K + k]; }
    tsum[tbP + k] = sP;
    tsum[tbQ + k] = sQ;
  }
  if (threadIdx.x < 32) {
    float wa = 0.f, wb = 0.f;
    #pragma unroll
    for (int i = 0; i < TS / 32; ++i) {
      wa += wp[threadIdx.x + 32 * i];
      wb += wq[threadIdx.x + 32 * i];
    }
    #pragma unroll
    for (int o = 16; o; o >>= 1) {
      wa += __shfl_down_sync(0xffffffffu, wa, o);
      wb += __shfl_down_sync(0xffffffffu, wb, o);
    }
    if (threadIdx.x == 0) { tsum[tbP + K] = wa; tsum[tbQ + K] = wb; }
  }
}

// ---------------- scan pass C: offsets from tsum + tile-local scans --------
template<int L>
__global__ void scanC_kernel() {
  constexpr int K = LP<L>::K;
  const float* feat = (L == 0) ? g_feat0 : g_feat1;
  const int*   perm = (L == 0) ? g_perm0 : g_perm1;
  const float* wPg = (L == 0) ? g_wP0 : g_wP1;
  const float* wQg = (L == 0) ? g_wQ0 : g_wQ1;
  const float* tsum = (L == 0) ? g_ts0 : g_ts1;
  float* pref = (L == 0) ? g_pref0 : g_pref1;
  __shared__ float vs[TS * K];
  __shared__ float wPs[TS], wQs[TS];
  __shared__ int pm[TS];
  int bh = blockIdx.x, tile = blockIdx.y, pos0 = tile * TS;
  int tid = threadIdx.x;
  if (tid < TS) {
    size_t o = (size_t)bh * NN + pos0 + tid;
    pm[tid] = perm[o];
    wPs[tid] = wPg[o];
    wQs[tid] = wQg[o];
  }
  __syncthreads();
  const float* fe = feat + (size_t)bh * NN * K;
  for (int e = tid; e < TS * K; e += 256) {
    int i = e / K, k = e % K;
    vs[e] = fe[(size_t)pm[i] * K + k];
  }
  __syncthreads();
  if (tid <= K) {
    int d = tid;
    size_t cb = (size_t)(bh * 2) * NT;
    float run = 0.f;
    for (int tt = 0; tt < tile; ++tt) run += tsum[(cb + tt) * (K + 1) + d];
    float* outP = pref + ((size_t)(bh * 2) * (NN + 1) + pos0) * (K + 1) + d;
    if (d < K) {
      for (int i = 0; i < TS; ++i) {
        outP[(size_t)i * (K + 1)] = run;
        run = fmaf(wPs[i], vs[i * K + d], run);
      }
    } else {
      for (int i = 0; i < TS; ++i) {
        outP[(size_t)i * (K + 1)] = run;
        run += wPs[i];
      }
    }
    if (tile == NT - 1)
      pref[((size_t)(bh * 2) * (NN + 1) + NN) * (K + 1) + d] = run;  // P total
  } else if (tid >= 128 && tid <= 128 + K) {
    int d = tid - 128;
    size_t cb = (size_t)(bh * 2 + 1) * NT;
    float run = 0.f;
    for (int tt = tile + 1; tt < NT; ++tt) run += tsum[(cb + tt) * (K + 1) + d];
    float* outQ = pref + ((size_t)(bh * 2 + 1) * (NN + 1) + pos0) * (K + 1) + d;
    if (d < K) {
      for (int i = TS - 1; i >= 0; --i) {
        run = fmaf(wQs[i], vs[i * K + d], run);
        outQ[(size_t)i * (K + 1)] = run;
      }
    } else {
      for (int i = TS - 1; i >= 0; --i) {
        run += wQs[i];
        outQ[(size_t)i * (K + 1)] = run;
      }
    }
    if (tile == NT - 1)
      pref[((size_t)(bh * 2 + 1) * (NN + 1) + NN) * (K + 1) + d] = 0.f;
  }
}

// ---------------- per-row combine: parallel search + prefix gather ----------
template<int L>
__global__ void rows_kernel(const float* __restrict__ bias,
                            float* __restrict__ outext) {
  constexpr int K = LP<L>::K, H = LP<L>::H;
  constexpr bool ELU = (L == 0);
  constexpr int RPB = 128;
  const float* ssrc  = (L == 0) ? g_ssrc0 : g_ssrc1;
  const float* sortd = (L == 0) ? g_sortd0 : g_sortd1;
  const float* pref  = (L == 0) ? g_pref0 : g_pref1;
  const float* dmaxA = (L == 0) ? g_dmax0 : g_dmax1;
  float* out = (L == 0) ? g_cat : outext;

  int bh = blockIdx.x;
  __shared__ float sd[NN];
  __shared__ int   ms[RPB];
  __shared__ float al[RPB], be[RPB];
  __shared__ float bs[K];
  for (int i = threadIdx.x; i < NN; i += 256) sd[i] = sortd[(size_t)bh * NN + i];
  const float* prefP = pref + (size_t)(bh * 2) * (NN + 1) * (K + 1);
  const float* prefQ = prefP + (size_t)(NN + 1) * (K + 1);
  if (threadIdx.x < K) bs[threadIdx.x] = bias[threadIdx.x];
  __syncthreads();

  float dmax = dmaxA[bh];
  int row0 = blockIdx.y * RPB;

  if (threadIdx.x < RPB) {
    int r = row0 + threadIdx.x;
    float s = ssrc[(size_t)bh * NN + r];
    float T = s + dmax;
    if (T > 0.f) { al[threadIdx.x] = 1.f; be[threadIdx.x] = expf(-0.8f * T); }
    else         { al[threadIdx.x] = expf(0.8f * T); be[threadIdx.x] = 1.f; }
    float thr = -s;
    int lo = 0, hi = NN;
    while (lo < hi) {
      int mid = (lo + hi) >> 1;
      if (sd[mid] > thr) lo = mid + 1; else hi = mid;
    }
    ms[threadIdx.x] = lo;
  }
  __syncthreads();

  int warp = threadIdx.x >> 5, lane = threadIdx.x & 31;
  int b = bh / H, h = bh % H;
  for (int rr = warp; rr < RPB; rr += 8) {
    int r = row0 + rr;
    int m = ms[rr];
    float alpha = al[rr], beta = be[rr];
    const float* pP = prefP + (size_t)m * (K + 1);
    const float* pQ = prefQ + (size_t)m * (K + 1);
    float den = alpha * pP[K] + beta * pQ[K];
    float inv = 1.f / den;
    #pragma unroll
    for (int k = lane; k < K; k += 32) {
      float num = alpha * pP[k] + beta * pQ[k];
      float v = num * inv + bs[k];
      size_t oi = ((size_t)b * NN + r) * (size_t)(H * K) + (size_t)h * K + k;
      if (ELU) out[oi] = (v > 0.f) ? v : (expf(v) - 1.f);
      else     out[oi] = v;
    }
  }
}

// ---------------- launch ----------------------------------------------------
extern "C" void kernel_launch(void* const* d_in, const int* in_sizes, int n_in,
                              void* d_out, int out_size) {
  (void)in_sizes; (void)n_in; (void)out_size;
  const float* x      = (const float*)d_in[0];
  const float* w0     = (const float*)d_in[1];
  const float* a_src0 = (const float*)d_in[2];
  const float* a_dst0 = (const float*)d_in[3];
  const float* b0     = (const float*)d_in[4];
  const float* w1     = (const float*)d_in[5];
  const float* a_src1 = (const float*)d_in[6];
  const float* a_dst1 = (const float*)d_in[7];
  const float* b1     = (const float*)d_in[8];
  float* out = (float*)d_out;

  // ---- layer 0 ----
  stats_part_kernel<0><<<dim3(NB, NSLAB), 256>>>(x);
  fold_kernel<0><<<NB, 128>>>(w0);
  gemm_kernel<0><<<dim3(NB, NN / 64), 256>>>(x, a_src0, a_dst0);
  sort_kernel<0><<<16, 512>>>();
  scanA_kernel<0><<<dim3(16, NT), 128>>>();
  scanC_kernel<0><<<dim3(16, NT), 256>>>();
  rows_kernel<0><<<dim3(16, NN / 128), 256>>>(b0, nullptr);

  // ---- layer 1 ----
  stats_part_kernel<1><<<dim3(NB, NSLAB), 256>>>(nullptr);
  fold_kernel<1><<<NB, 128>>>(w1);
  gemm_kernel<1><<<dim3(NB, NN / 32), 256>>>(nullptr, a_src1, a_dst1);
  sort_kernel<1><<<4, 512>>>();
  scanA_kernel<1><<<dim3(4, NT), 128>>>();
  scanC_kernel<1><<<dim3(4, NT), 256>>>();
  rows_kernel<1><<<dim3(4, NN / 128), 256>>>(b1, out);
}